// round 17
// baseline (speedup 1.0000x reference)
#include <cuda_runtime.h>
#include <math_constants.h>

#define NROWS 8192
#define F     256
#define ALPHA 0.2f

// Scratch (allocation-free rule: __device__ globals; zero-initialized)
__device__ __align__(16) float g_u1[F];
__device__ __align__(16) float g_u2[F];
__device__ __align__(16) float g_s1[NROWS];
__device__ __align__(16) float g_s2[NROWS];
__device__ int g_flag;   // producer-CTA completion count; reset by kernel C each run

// ---------------------------------------------------------------------------
// Fused kernel A+B:
//   phase 1 (CTAs 0..31): u1[r]=W[r,:]·a[:256], u2[r]=W[r,:]·a[256:]
//                         warp-per-row, coalesced float4 (measured-good form)
//   phase 2 (all CTAs):   s1[i]=src[i,:]·u1, s2[i]=src[i,:]·u2, 4 rows/warp
// Handshake: producers __threadfence + atomicAdd(g_flag); consumers prefetch
// their src rows into registers FIRST (independent of u), then spin on an
// acquire load of g_flag. grid=256 CTAs with __launch_bounds__(256,2):
// 256 <= 148*2 so ALL CTAs are resident in wave 1 -> spin is deadlock-free.
// ---------------------------------------------------------------------------
__global__ void __launch_bounds__(256, 2) fused_su_kernel(const float* __restrict__ src,
                                                          const float* __restrict__ W,
                                                          const float* __restrict__ a) {
    const int t    = threadIdx.x;
    const int wid  = t >> 5;
    const int lane = t & 31;
    const int gw   = blockIdx.x * 8 + wid;    // global warp 0..2047

    // ---- prefetch 4 src rows into registers (independent of u) ----
    const int row0 = gw * 4;
    float4 x[4][2];
#pragma unroll
    for (int r = 0; r < 4; r++) {
        const float4* srow = reinterpret_cast<const float4*>(src + (size_t)(row0 + r) * F);
        x[r][0] = srow[lane];
        x[r][1] = srow[lane + 32];
    }

    // ---- phase 1: first 32 CTAs compute u (warp-per-row) ----
    if (blockIdx.x < 32) {
        const float4* wrow = reinterpret_cast<const float4*>(W + (size_t)gw * F);
        const float4* a1v  = reinterpret_cast<const float4*>(a);       // a[0:256]
        const float4* a2v  = reinterpret_cast<const float4*>(a + F);   // a[256:512]
        float u1 = 0.f, u2 = 0.f;
#pragma unroll
        for (int i = 0; i < 2; i++) {
            int idx = lane + i * 32;
            float4 w = wrow[idx];
            float4 p = __ldg(&a1v[idx]);
            float4 q = __ldg(&a2v[idx]);
            u1 += w.x * p.x + w.y * p.y + w.z * p.z + w.w * p.w;
            u2 += w.x * q.x + w.y * q.y + w.z * q.z + w.w * q.w;
        }
#pragma unroll
        for (int o = 16; o > 0; o >>= 1) {
            u1 += __shfl_xor_sync(0xffffffffu, u1, o);
            u2 += __shfl_xor_sync(0xffffffffu, u2, o);
        }
        if (lane == 0) {
            g_u1[gw] = u1;
            g_u2[gw] = u2;
        }
        __syncthreads();                      // all 8 u-rows of this CTA done
        if (t == 0) {
            __threadfence();                  // publish g_u before flag bump
            atomicAdd(&g_flag, 1);
        }
    }

    // ---- wait for all 32 producer CTAs (one polling thread per CTA) ----
    if (t == 0) {
        int f;
        do {
            asm volatile("ld.acquire.gpu.b32 %0, [%1];"
                         : "=r"(f) : "l"(&g_flag) : "memory");
            if (f < 32) __nanosleep(64);
        } while (f < 32);
    }
    __syncthreads();

    // ---- phase 2: s1/s2 for this warp's 4 rows (u now L2-hot) ----
    const float4* u1v = reinterpret_cast<const float4*>(g_u1);
    const float4* u2v = reinterpret_cast<const float4*>(g_u2);
    const float4 p0 = u1v[lane], p1 = u1v[lane + 32];
    const float4 q0 = u2v[lane], q1 = u2v[lane + 32];
#pragma unroll
    for (int r = 0; r < 4; r++) {
        float s1 = x[r][0].x * p0.x + x[r][0].y * p0.y + x[r][0].z * p0.z + x[r][0].w * p0.w
                 + x[r][1].x * p1.x + x[r][1].y * p1.y + x[r][1].z * p1.z + x[r][1].w * p1.w;
        float s2 = x[r][0].x * q0.x + x[r][0].y * q0.y + x[r][0].z * q0.z + x[r][0].w * q0.w
                 + x[r][1].x * q1.x + x[r][1].y * q1.y + x[r][1].z * q1.z + x[r][1].w * q1.w;
#pragma unroll
        for (int o = 16; o > 0; o >>= 1) {
            s1 += __shfl_xor_sync(0xffffffffu, s1, o);
            s2 += __shfl_xor_sync(0xffffffffu, s2, o);
        }
        if (lane == 0) {
            g_s1[row0 + r] = s1;
            g_s2[row0 + r] = s2;
        }
    }
}

// ---------------------------------------------------------------------------
// Kernel C: fused e / leakyrelu / +bias / row-softmax, single pass over bias.
// One CTA per row, 512 threads, 4 float4 per thread in registers.
// __launch_bounds__(512,2) caps regs at 64 -> guarantees 2 CTAs/SM.
// Also resets g_flag for the next graph replay (block 0 only).
// ---------------------------------------------------------------------------
__device__ __forceinline__ float lrelu(float x) {
    return x > 0.f ? x : ALPHA * x;
}

#define CTHREADS 512
#define NWARPS   (CTHREADS / 32)
#define VPT      4    // float4 per thread; CTHREADS*VPT*4 == NROWS

__global__ void __launch_bounds__(CTHREADS, 2) softmax_row_kernel(const float* __restrict__ bias,
                                                                  float* __restrict__ out) {
    const int row  = blockIdx.x;
    const int t    = threadIdx.x;
    const int lane = t & 31;
    const int wid  = t >> 5;          // 0..15

    if (row == 0 && t == 0) g_flag = 0;   // reset handshake for next replay

    const float s1 = g_s1[row];
    const float4* brow = reinterpret_cast<const float4*>(bias + (size_t)row * NROWS);
    float4*       orow = reinterpret_cast<float4*>(out + (size_t)row * NROWS);
    const float4* s2v  = reinterpret_cast<const float4*>(g_s2);

    // ---- load phase: 8 independent loads issued back-to-back ----
    float4 b[VPT], s[VPT];
#pragma unroll
    for (int i = 0; i < VPT; i++)
        b[i] = __ldcs(&brow[t + i * CTHREADS]);   // streaming, evict-first
#pragma unroll
    for (int i = 0; i < VPT; i++)
        s[i] = s2v[t + i * CTHREADS];             // L2-resident broadcast

    // ---- compute phase: e = lrelu(s1 + s2) + bias, warp-local max ----
    float4 e[VPT];
    float mx = -CUDART_INF_F;
#pragma unroll
    for (int i = 0; i < VPT; i++) {
        float4 v;
        v.x = lrelu(s1 + s[i].x) + b[i].x;
        v.y = lrelu(s1 + s[i].y) + b[i].y;
        v.z = lrelu(s1 + s[i].z) + b[i].z;
        v.w = lrelu(s1 + s[i].w) + b[i].w;
        e[i] = v;
        mx = fmaxf(mx, fmaxf(fmaxf(v.x, v.y), fmaxf(v.z, v.w)));
    }
#pragma unroll
    for (int o = 16; o > 0; o >>= 1)
        mx = fmaxf(mx, __shfl_xor_sync(0xffffffffu, mx, o));
    // mx is now the warp max (uniform within warp)

    // ---- exp relative to warp max, warp-local sum ----
    float sum = 0.f;
#pragma unroll
    for (int i = 0; i < VPT; i++) {
        e[i].x = __expf(e[i].x - mx);
        e[i].y = __expf(e[i].y - mx);
        e[i].z = __expf(e[i].z - mx);
        e[i].w = __expf(e[i].w - mx);
        sum += (e[i].x + e[i].y) + (e[i].z + e[i].w);
    }
#pragma unroll
    for (int o = 16; o > 0; o >>= 1)
        sum += __shfl_xor_sync(0xffffffffu, sum, o);

    // ---- combine 16 warp (max, sum) pairs: single barrier ----
    __shared__ float2 wred[NWARPS];
    if (lane == 0) wred[wid] = make_float2(mx, sum);
    __syncthreads();

    float M = -CUDART_INF_F;
#pragma unroll
    for (int w = 0; w < NWARPS; w++)
        M = fmaxf(M, wred[w].x);
    float S = 0.f;
#pragma unroll
    for (int w = 0; w < NWARPS; w++)
        S += wred[w].y * __expf(wred[w].x - M);

    // elements hold exp(v - mx_warp); final weight is
    // exp(v - M)/S = exp(v - mx_warp) * exp(mx_warp - M) / S
    const float corr = __expf(mx - M) * __frcp_rn(S);

    // ---- scaled streaming store ----
#pragma unroll
    for (int i = 0; i < VPT; i++) {
        float4 v = e[i];
        v.x *= corr; v.y *= corr; v.z *= corr; v.w *= corr;
        __stcs(&orow[t + i * CTHREADS], v);       // streaming, evict-first
    }
}

// ---------------------------------------------------------------------------
extern "C" void kernel_launch(void* const* d_in, const int* in_sizes, int n_in,
                              void* d_out, int out_size) {
    // Resolve inputs by unique element counts (robust to metadata ordering):
    //   src  : 8192*256   = 2097152
    //   bias : 8192*8192  = 67108864
    //   W    : 256*256    = 65536
    //   a    : 512*1      = 512
    const float* src  = nullptr;
    const float* bias = nullptr;
    const float* W    = nullptr;
    const float* a    = nullptr;
    for (int i = 0; i < n_in; i++) {
        switch (in_sizes[i]) {
            case 2097152:  src  = (const float*)d_in[i]; break;
            case 67108864: bias = (const float*)d_in[i]; break;
            case 65536:    W    = (const float*)d_in[i]; break;
            case 512:      a    = (const float*)d_in[i]; break;
        }
    }
    float* out = (float*)d_out;  // [8192, 8192]

    fused_su_kernel<<<256, 256>>>(src, W, a);
    softmax_row_kernel<<<NROWS, CTHREADS>>>(bias, out);
}